// round 13
// baseline (speedup 1.0000x reference)
#include <cuda_runtime.h>
#include <cuda_fp16.h>
#include <cstdint>

#define Bb   128
#define Tt   256
#define Dd   384
#define Hh   6
#define HD   64
#define ROWS (Bb*Tt)          // 32768
#define DFF  (4*Dd)           // 1536

// ------------------------- scratch (device globals) -------------------------
__device__ __half g_Hb[ROWS * Dd];
__device__ __half g_QKVb[ROWS * 3 * Dd];
__device__ __half g_Ob[ROWS * Dd];
__device__ __half g_X1h[ROWS * Dd];       // x + attn proj, fp16
__device__ __half g_A1b[ROWS * DFF];
__device__ __half g_WQKVt[3*Dd * Dd];     // [1152,384] K-major
__device__ __half g_Wpt[Dd * Dd];
__device__ __half g_W1t[DFF * Dd];
__device__ __half g_W2t[Dd * DFF];

// ------------------------------ helpers ------------------------------
__device__ __forceinline__ uint32_t smem_u32(const void* p) {
    uint32_t a;
    asm("{ .reg .u64 t; cvta.to.shared.u64 t, %1; cvt.u32.u64 %0, t; }" : "=r"(a) : "l"(p));
    return a;
}

#define GDC_WAIT()  asm volatile("griddepcontrol.wait;" ::: "memory")
#define GDC_TRIG()  asm volatile("griddepcontrol.launch_dependents;" ::: "memory")

#define CPA(dst, src) \
    asm volatile("cp.async.cg.shared.global [%0], [%1], 16;" :: "r"(dst), "l"(src))
#define CPA_COMMIT() asm volatile("cp.async.commit_group;" ::: "memory")

#define LDSM4(r0, r1, r2, r3, a) \
    asm volatile("ldmatrix.sync.aligned.m8n8.x4.shared.b16 {%0,%1,%2,%3}, [%4];" \
                 : "=r"(r0), "=r"(r1), "=r"(r2), "=r"(r3) : "r"(a))
#define LDSM4T(r0, r1, r2, r3, a) \
    asm volatile("ldmatrix.sync.aligned.m8n8.x4.trans.shared.b16 {%0,%1,%2,%3}, [%4];" \
                 : "=r"(r0), "=r"(r1), "=r"(r2), "=r"(r3) : "r"(a))

// fp16 inputs, fp32 accumulators (attention)
#define MMA16816F(d, a0, a1, a2, a3, b0, b1) \
    asm volatile("mma.sync.aligned.m16n8k16.row.col.f32.f16.f16.f32 " \
                 "{%0,%1,%2,%3}, {%4,%5,%6,%7}, {%8,%9}, {%0,%1,%2,%3};" \
                 : "+f"((d)[0]), "+f"((d)[1]), "+f"((d)[2]), "+f"((d)[3]) \
                 : "r"(a0), "r"(a1), "r"(a2), "r"(a3), "r"(b0), "r"(b1))

// fp16 inputs, fp16 accumulators (GEMMs)
#define MMA16816H(d, a0, a1, a2, a3, b0, b1) \
    asm volatile("mma.sync.aligned.m16n8k16.row.col.f16.f16.f16.f16 " \
                 "{%0,%1}, {%2,%3,%4,%5}, {%6,%7}, {%0,%1};" \
                 : "+r"((d)[0]), "+r"((d)[1]) \
                 : "r"(a0), "r"(a1), "r"(a2), "r"(a3), "r"(b0), "r"(b1))

__device__ __forceinline__ uint32_t pkhf(float a, float b) {
    __half2 t = __floats2half2_rn(a, b);
    return *reinterpret_cast<uint32_t*>(&t);
}
#define PKH2(d, a, b) \
    asm("cvt.rn.f16x2.f32 %0, %2, %1;" : "=r"(d) : "f"(a), "f"(b))
#define EX2H2(r) asm("ex2.approx.f16x2 %0, %0;" : "+r"(r))

// ------------------- fused LN1 + weight pack -------------------
#define LN_BLKS (ROWS/8)
#define PACK_TOTAL (2*Dd*Dd + 2*Dd*DFF)
#define PK_BLKS ((PACK_TOTAL + 255)/256)

__global__ void __launch_bounds__(256) ln1_pack(
    const float* __restrict__ x, const float* __restrict__ g, const float* __restrict__ be,
    __half* __restrict__ out,
    const float* __restrict__ Wq, const float* __restrict__ Wk, const float* __restrict__ Wv,
    const float* __restrict__ Wp, const float* __restrict__ W1, const float* __restrict__ W2,
    __half* __restrict__ WQKVt, __half* __restrict__ Wpt,
    __half* __restrict__ W1t,   __half* __restrict__ W2t)
{
    const int tid = threadIdx.x;
    if (blockIdx.x < LN_BLKS) {
        const int w = tid >> 5, l = tid & 31;
        const int row = blockIdx.x * 8 + w;
        const float* xr = x + (size_t)row * Dd;
        float4 v[3];
#pragma unroll
        for (int i = 0; i < 3; i++) v[i] = *(const float4*)(xr + i * 128 + l * 4);
        float s = 0.f, sq = 0.f;
#pragma unroll
        for (int i = 0; i < 3; i++) {
            s  += v[i].x + v[i].y + v[i].z + v[i].w;
            sq += v[i].x*v[i].x + v[i].y*v[i].y + v[i].z*v[i].z + v[i].w*v[i].w;
        }
#pragma unroll
        for (int o = 16; o; o >>= 1) {
            s  += __shfl_xor_sync(0xffffffffu, s,  o);
            sq += __shfl_xor_sync(0xffffffffu, sq, o);
        }
        const float mean = s * (1.0f / Dd);
        const float var  = sq * (1.0f / Dd) - mean * mean;
        const float rstd = rsqrtf(var + 1e-5f);
        __half* orow = out + (size_t)row * Dd;
#pragma unroll
        for (int i = 0; i < 3; i++) {
            const int c = i * 128 + l * 4;
            const float4 gg = *(const float4*)(g + c);
            const float4 bb = *(const float4*)(be + c);
            uint2 o;
            o.x = pkhf((v[i].x - mean) * rstd * gg.x + bb.x,
                       (v[i].y - mean) * rstd * gg.y + bb.y);
            o.y = pkhf((v[i].z - mean) * rstd * gg.z + bb.z,
                       (v[i].w - mean) * rstd * gg.w + bb.w);
            *(uint2*)(orow + c) = o;
        }
    } else {
        int idx = (blockIdx.x - LN_BLKS) * 256 + tid;
        if (idx >= PACK_TOTAL) return;
        const int n1 = Dd * Dd, n2 = 2 * Dd * Dd, n3 = 2 * Dd * Dd + Dd * DFF;
        if (idx < n1) {
            int d = idx / Dd, col = idx % Dd;
            int h = col >> 6, k = col & 63;
            int src = h * (Dd * HD) + d * HD + k;
            WQKVt[(size_t)col * Dd + d]          = __float2half_rn(Wq[src]);
            WQKVt[(size_t)(Dd + col) * Dd + d]   = __float2half_rn(Wk[src]);
            WQKVt[(size_t)(2*Dd + col) * Dd + d] = __float2half_rn(Wv[src]);
        } else if (idx < n2) {
            int i = idx - n1;
            int n = i / Dd, d = i % Dd;
            Wpt[(size_t)n * Dd + d] = __float2half_rn(Wp[(size_t)d * Dd + n]);
        } else if (idx < n3) {
            int i = idx - n2;
            int n = i / Dd, d = i % Dd;
            W1t[(size_t)n * Dd + d] = __float2half_rn(W1[(size_t)d * DFF + n]);
        } else {
            int i = idx - n3;
            int n = i / DFF, d = i % DFF;
            W2t[(size_t)n * DFF + d] = __float2half_rn(W2[(size_t)d * Dd + n]);
        }
    }
}

// ------------------------------ LayerNorm (LN2, fp16 in, PDL) ------------------------------
__global__ void __launch_bounds__(256) ln2_kernel(const __half* __restrict__ x,
                                                  const float* __restrict__ g,
                                                  const float* __restrict__ be,
                                                  __half* __restrict__ out)
{
    GDC_WAIT();
    GDC_TRIG();
    const int w = threadIdx.x >> 5, l = threadIdx.x & 31;
    const int row = blockIdx.x * 8 + w;
    const __half* xr = x + (size_t)row * Dd;
    float4 v[3];
#pragma unroll
    for (int i = 0; i < 3; i++) {
        uint2 raw = *(const uint2*)(xr + i * 128 + l * 4);
        float2 f01 = __half22float2(*reinterpret_cast<__half2*>(&raw.x));
        float2 f23 = __half22float2(*reinterpret_cast<__half2*>(&raw.y));
        v[i] = make_float4(f01.x, f01.y, f23.x, f23.y);
    }
    float s = 0.f, sq = 0.f;
#pragma unroll
    for (int i = 0; i < 3; i++) {
        s  += v[i].x + v[i].y + v[i].z + v[i].w;
        sq += v[i].x*v[i].x + v[i].y*v[i].y + v[i].z*v[i].z + v[i].w*v[i].w;
    }
#pragma unroll
    for (int o = 16; o; o >>= 1) {
        s  += __shfl_xor_sync(0xffffffffu, s,  o);
        sq += __shfl_xor_sync(0xffffffffu, sq, o);
    }
    const float mean = s * (1.0f / Dd);
    const float var  = sq * (1.0f / Dd) - mean * mean;
    const float rstd = rsqrtf(var + 1e-5f);
    __half* orow = out + (size_t)row * Dd;
#pragma unroll
    for (int i = 0; i < 3; i++) {
        const int c = i * 128 + l * 4;
        const float4 gg = *(const float4*)(g + c);
        const float4 bb = *(const float4*)(be + c);
        uint2 o;
        o.x = pkhf((v[i].x - mean) * rstd * gg.x + bb.x,
                   (v[i].y - mean) * rstd * gg.y + bb.y);
        o.y = pkhf((v[i].z - mean) * rstd * gg.z + bb.z,
                   (v[i].w - mean) * rstd * gg.w + bb.w);
        *(uint2*)(orow + c) = o;
    }
}

// ------------------------------- fp16 HMMA GEMM v6 -------------------------------
// 128x128 CTA tile, 8 warps (warp tile 32x64), 3-stage pipeline, 3 CTAs/SM
// (24 warps/SM = 6/SMSP for latency hiding on short-K GEMMs).
// EPI bits: 1=bias 2=relu 4=resid. RESHF: resid fp16. OHF: output fp16.
#define GOP_B   10240
#define GSTG_B  (2*GOP_B)
#define GNST    3
#define GEMM_SMEM (GNST*GSTG_B)  // 61440

template <int EPI, bool OHF, bool RESHF>
__global__ void __launch_bounds__(256, 3)
gemm_tc(const __half* __restrict__ A, const __half* __restrict__ B,
        void* __restrict__ Cv, int N, int K,
        const float* __restrict__ bias, const void* __restrict__ resid)
{
    extern __shared__ char smg[];
    const uint32_t s0 = smem_u32(smg);
    const int tid = threadIdx.x, w = tid >> 5, l = tid & 31;
    const int bn = blockIdx.x * 128, bm = blockIdx.y * 128;
    const int wm = w & 3, wn = w >> 2;   // 4 m-warps x 2 n-warps

    // global load: 256 threads, rows lr & lr+64, 8-half chunk lc
    const int lc = tid & 3, lr = tid >> 2;
    const __half* Ag = A + (size_t)(bm + lr) * K + lc * 8;
    const __half* Bg = B + (size_t)(bn + lr) * K + lc * 8;
    const uint32_t stoff = (uint32_t)(lr * 40 + lc * 8) * 2;

    uint32_t hacc[2][8][2];
#pragma unroll
    for (int i = 0; i < 2; i++)
#pragma unroll
        for (int j = 0; j < 8; j++) { hacc[i][j][0] = 0u; hacc[i][j][1] = 0u; }

    const int S = K / 32;

#define GA_ISSUE(p) do { \
    const uint32_t dst = s0 + ((p) % GNST) * GSTG_B; \
    const __half* ag = Ag + (p) * 32; \
    CPA(dst + stoff,        ag); \
    CPA(dst + stoff + 5120, ag + (size_t)64 * K); \
} while (0)
#define GB_ISSUE(p) do { \
    const uint32_t dst = s0 + ((p) % GNST) * GSTG_B + GOP_B; \
    const __half* bg = Bg + (p) * 32; \
    CPA(dst + stoff,        bg); \
    CPA(dst + stoff + 5120, bg + (size_t)64 * K); \
} while (0)

    // weight stages pre-wait (overlap producer tail); activations post-wait
    GB_ISSUE(0); CPA_COMMIT();
    GB_ISSUE(1); CPA_COMMIT();
    GDC_WAIT();
    GA_ISSUE(0); CPA_COMMIT();
    GA_ISSUE(1); CPA_COMMIT();

    // ldmatrix lane addressing (round-3 proven patterns)
    const int arow = ((l >> 3) & 1) * 8 + (l & 7);
    const uint32_t aBase = s0 + (uint32_t)((wm * 32 + arow) * 80) + (l >> 4) * 16;
    const int brow = (l >> 4) * 8 + (l & 7);
    const uint32_t bBase = s0 + GOP_B + (uint32_t)((wn * 64 + brow) * 80) + ((l >> 3) & 1) * 16;

    uint32_t af[2][4], bf[8][2];

#define G_LOADFRAG(ab, bb, ks) do { \
    _Pragma("unroll") \
    for (int mt = 0; mt < 2; mt++) \
        LDSM4(af[mt][0], af[mt][1], af[mt][2], af[mt][3], \
              (ab) + mt * 1280 + (ks) * 32); \
    _Pragma("unroll") \
    for (int pr = 0; pr < 4; pr++) { \
        uint32_t t0, t1, t2, t3; \
        LDSM4(t0, t1, t2, t3, (bb) + pr * 1280 + (ks) * 32); \
        bf[2*pr][0] = t0; bf[2*pr][1] = t1; \
        bf[2*pr+1][0] = t2; bf[2*pr+1][1] = t3; \
    } } while (0)

#define G_MMA() do { \
    _Pragma("unroll") \
    for (int mt = 0; mt < 2; mt++) \
        _Pragma("unroll") \
        for (int nt = 0; nt < 8; nt++) \
            MMA16816H(hacc[mt][nt], af[mt][0], af[mt][1], \
                      af[mt][2], af[mt][3], bf[nt][0], bf[nt][1]); \
    } while (0)

    for (int s = 0; s < S; s++) {
        asm volatile("cp.async.wait_group 1;" ::: "memory");
        __syncthreads();
        if (s + 2 < S) { GA_ISSUE(s + 2); GB_ISSUE(s + 2); }
        CPA_COMMIT();

        const uint32_t off = (uint32_t)((s % GNST) * GSTG_B);
        G_LOADFRAG(aBase + off, bBase + off, 0);
        G_MMA();
        G_LOADFRAG(aBase + off, bBase + off, 1);
        G_MMA();
    }
#undef GA_ISSUE
#undef GB_ISSUE
#undef G_LOADFRAG
#undef G_MMA

    GDC_TRIG();

    const int qr = l >> 2, qc = (l & 3) * 2;
#pragma unroll
    for (int mt = 0; mt < 2; mt++) {
#pragma unroll
        for (int half = 0; half < 2; half++) {
            const int r = bm + wm * 32 + mt * 16 + qr + half * 8;
#pragma unroll
            for (int nt = 0; nt < 8; nt++) {
                const int c = bn + wn * 64 + nt * 8 + qc;
                float2 vv = __half22float2(
                    *reinterpret_cast<__half2*>(&hacc[mt][nt][half]));
                float v0 = vv.x, v1 = vv.y;
                if (EPI & 1) { v0 += bias[c]; v1 += bias[c + 1]; }
                if (EPI & 2) { v0 = fmaxf(v0, 0.0f); v1 = fmaxf(v1, 0.0f); }
                if (EPI & 4) {
                    if (RESHF) {
                        uint32_t rr = *(const uint32_t*)((const __half*)resid + (size_t)r * N + c);
                        float2 rf = __half22float2(*reinterpret_cast<__half2*>(&rr));
                        v0 += rf.x; v1 += rf.y;
                    } else {
                        float2 rv = *(const float2*)((const float*)resid + (size_t)r * N + c);
                        v0 += rv.x; v1 += rv.y;
                    }
                }
                if (OHF) {
                    *(uint32_t*)((__half*)Cv + (size_t)r * N + c) = pkhf(v0, v1);
                } else {
                    *(float2*)((float*)Cv + (size_t)r * N + c) = make_float2(v0, v1);
                }
            }
        }
    }
}

// --------------------------- Attention (HMMA flash, f16x2 softmax) ---------------------------
#define KV_PITCH 72

__global__ void __launch_bounds__(256, 3) attn_kernel(const __half* __restrict__ QKV,
                                                      __half* __restrict__ O)
{
    GDC_WAIT();
    extern __shared__ __align__(16) __half smkv[];
    const uint32_t sK = smem_u32(smkv);
    const uint32_t sV = sK + Tt * KV_PITCH * 2;
    const int bh = blockIdx.x;
    const int b = bh / Hh, h = bh % Hh;
    const int tid = threadIdx.x;
    const __half* base = QKV + (size_t)b * Tt * (3*Dd) + h * HD;

    for (int idx = tid; idx < 2 * 2048; idx += 256) {
        int half = idx >> 11, i = idx & 2047;
        int row = i >> 3, c8 = i & 7;
        const uint4 v = *(const uint4*)(base + (size_t)row * (3*Dd) + (half + 1) * Dd + c8 * 8);
        *(uint4*)((char*)smkv + (half ? (size_t)Tt * KV_PITCH * 2 : 0)
                  + row * (KV_PITCH*2) + c8 * 16) = v;
    }
    __syncthreads();

    const int w = tid >> 5, l = tid & 31;
    const int qr = l >> 2, qc = l & 3;

    const uint32_t kAddr = sK + (uint32_t)(((l >> 4) * 8 + (l & 7)) * (KV_PITCH*2))
                               + ((l >> 3) & 1) * 16;
    const uint32_t vAddr = sV + (uint32_t)((((l >> 3) & 1) * 8 + (l & 7)) * (KV_PITCH*2))
                               + ((l >> 4) & 1) * 16;

    const float sc2 = rsqrtf((float)Dd) * 1.4426950408889634f;

#pragma unroll
    for (int job = 0; job < 2; job++) {
        const int bt = job ? 16 * (15 - w) : 16 * w;
        const int nch = job ? (16 - w) : (w + 1);

        const __half* Qrow = base + (size_t)bt * (3*Dd);
        uint32_t qa[4][4];
#pragma unroll
        for (int kc = 0; kc < 4; kc++) {
            int k0 = kc * 16 + qc * 2;
            qa[kc][0] = *(const uint32_t*)(Qrow + (size_t)qr * (3*Dd) + k0);
            qa[kc][1] = *(const uint32_t*)(Qrow + (size_t)(qr + 8) * (3*Dd) + k0);
            qa[kc][2] = *(const uint32_t*)(Qrow + (size_t)qr * (3*Dd) + k0 + 8);
            qa[kc][3] = *(const uint32_t*)(Qrow + (size_t)(qr + 8) * (3*Dd) + k0 + 8);
        }

        float oacc[8][4];
#pragma unroll
        for (int i = 0; i < 8; i++)
#pragma unroll
            for (int j = 0; j < 4; j++) oacc[i][j] = 0.0f;
        float l0 = 0.0f, l1 = 0.0f;

        for (int c = 0; c < nch; c++) {
            const uint32_t kRow = kAddr + c * 16 * (KV_PITCH*2);
            float s[2][4];
#pragma unroll
            for (int nt = 0; nt < 2; nt++)
#pragma unroll
                for (int j = 0; j < 4; j++) s[nt][j] = 0.0f;
#pragma unroll
            for (int kc = 0; kc < 4; kc++) {
                uint32_t k0, k1, k2, k3;
                LDSM4(k0, k1, k2, k3, kRow + kc * 32);
                MMA16816F(s[0], qa[kc][0], qa[kc][1], qa[kc][2], qa[kc][3], k0, k1);
                MMA16816F(s[1], qa[kc][0], qa[kc][1], qa[kc][2], qa[kc][3], k2, k3);
            }
            const bool maskc = (c == nch - 1);
#pragma unroll
            for (int nt = 0; nt < 2; nt++)
#pragma unroll
                for (int j = 0; j < 4; j++) {
                    float sv = fminf(s[nt][j] * sc2, 10.0f);
                    if (maskc) {
                        int trow = bt + qr + 8 * (j >> 1);
                        int scol = 16 * c + 8 * nt + 2 * qc + (j & 1);
                        if (scol > trow) sv = -60000.0f;
                    }
                    s[nt][j] = sv;
                }
            uint32_t pa0, pa1, pa2, pa3;
            PKH2(pa0, s[0][0], s[0][1]);
            PKH2(pa1, s[0][2], s[0][3]);
            PKH2(pa2, s[1][0], s[1][1]);
            PKH2(pa3, s[1][2], s[1][3]);
            EX2H2(pa0); EX2H2(pa1); EX2H2(pa2); EX2H2(pa3);
            {
                __half2 h0 = __hadd2(*reinterpret_cast<__half2*>(&pa0),
                                     *reinterpret_cast<__half2*>(&pa2));
                __half2 h1 = __hadd2(*reinterpret_cast<__half2*>(&pa1),
                                     *reinterpret_cast<__half2*>(&pa3));
                float2 f0 = __half22float2(h0), f1 = __half22float2(h1);
                l0 += f0.x + f0.y;
                l1 += f1.x + f1.y;
            }

            const uint32_t vRow = vAddr + c * 16 * (KV_PITCH*2);
#pragma unroll
            for (int g = 0; g < 4; g++) {
                uint32_t v0, v1, v2, v3;
                LDSM4T(v0, v1, v2, v3, vRow + g * 32);
                MMA16816F(oacc[2*g],     pa0, pa1, pa2, pa3, v0, v1);
                MMA16816F(oacc[2*g + 1], pa0, pa1, pa2, pa3, v2, v3);
            }
        }

        if (job == 1) GDC_TRIG();

        l0 += __shfl_xor_sync(0xffffffffu, l0, 1);
        l0 += __shfl_xor_sync(0xffffffffu, l0, 2);
        l1 += __shfl_xor_sync(0xffffffffu, l1, 1);
        l1 += __shfl_xor_sync(0xffffffffu, l1, 2);
        const float i0 = 1.0f / l0, i1 = 1.0f / l1;

        __half* Orow = O + ((size_t)b * Tt + bt) * Dd + h * HD;
#pragma unroll
        for (int dt = 0; dt < 8; dt++) {
            int col = dt * 8 + qc * 2;
            *(uint32_t*)(Orow + (size_t)qr * Dd + col) =
                pkhf(oacc[dt][0] * i0, oacc[dt][1] * i0);
            *(uint32_t*)(Orow + (size_t)(qr + 8) * Dd + col) =
                pkhf(oacc[dt][2] * i1, oacc[dt][3] * i1);
        }
    }
}

// ------------------------------- launch -------------------------------
template <typename F, typename... Args>
static void launch_pdl(F func, dim3 grid, dim3 block, size_t smem, Args... args)
{
    cudaLaunchConfig_t cfg = {};
    cfg.gridDim = grid; cfg.blockDim = block;
    cfg.dynamicSmemBytes = smem; cfg.stream = 0;
    cudaLaunchAttribute at[1];
    at[0].id = cudaLaunchAttributeProgrammaticStreamSerialization;
    at[0].val.programmaticStreamSerializationAllowed = 1;
    cfg.attrs = at; cfg.numAttrs = 1;
    cudaLaunchKernelEx(&cfg, func, args...);
}

extern "C" void kernel_launch(void* const* d_in, const int* in_sizes, int n_in,
                              void* d_out, int out_size)
{
    const float* x   = (const float*)d_in[0];
    const float* Wq  = (const float*)d_in[1];
    const float* Wk  = (const float*)d_in[2];
    const float* Wv  = (const float*)d_in[3];
    const float* Wp  = (const float*)d_in[4];
    const float* bp  = (const float*)d_in[5];
    const float* W1  = (const float*)d_in[6];
    const float* b1  = (const float*)d_in[7];
    const float* W2  = (const float*)d_in[8];
    const float* b2  = (const float*)d_in[9];
    const float* g1  = (const float*)d_in[10];
    const float* be1 = (const float*)d_in[11];
    const float* g2  = (const float*)d_in[12];
    const float* be2 = (const float*)d_in[13];
    float* out = (float*)d_out;

    __half *Hb, *QKVb, *Ob, *X1h, *A1b, *WQKVt, *Wpt, *W1t, *W2t;
    cudaGetSymbolAddress((void**)&Hb,    g_Hb);
    cudaGetSymbolAddress((void**)&QKVb,  g_QKVb);
    cudaGetSymbolAddress((void**)&Ob,    g_Ob);
    cudaGetSymbolAddress((void**)&X1h,   g_X1h);
    cudaGetSymbolAddress((void**)&A1b,   g_A1b);
    cudaGetSymbolAddress((void**)&WQKVt, g_WQKVt);
    cudaGetSymbolAddress((void**)&Wpt,   g_Wpt);
    cudaGetSymbolAddress((void**)&W1t,   g_W1t);
    cudaGetSymbolAddress((void**)&W2t,   g_W2t);

    const int ATTN_SMEM = Tt * KV_PITCH * 2 * 2;  // 73728
    cudaFuncSetAttribute(attn_kernel, cudaFuncAttributeMaxDynamicSharedMemorySize, ATTN_SMEM);
    cudaFuncSetAttribute(gemm_tc<0, true, false>,  cudaFuncAttributeMaxDynamicSharedMemorySize, GEMM_SMEM);
    cudaFuncSetAttribute(gemm_tc<5, true, false>,  cudaFuncAttributeMaxDynamicSharedMemorySize, GEMM_SMEM);
    cudaFuncSetAttribute(gemm_tc<3, true, false>,  cudaFuncAttributeMaxDynamicSharedMemorySize, GEMM_SMEM);
    cudaFuncSetAttribute(gemm_tc<5, false, true>,  cudaFuncAttributeMaxDynamicSharedMemorySize, GEMM_SMEM);

    // 1. LN1 + weight pack
    ln1_pack<<<LN_BLKS + PK_BLKS, 256>>>(x, g1, be1, Hb,
                                         Wq, Wk, Wv, Wp, W1, W2,
                                         WQKVt, Wpt, W1t, W2t);
    // 2. QKV = Hb @ WQKVt^T
    launch_pdl(gemm_tc<0, true, false>, dim3((3*Dd)/128, ROWS/128), dim3(256), (size_t)GEMM_SMEM,
               (const __half*)Hb, (const __half*)WQKVt, (void*)QKVb, 3*Dd, Dd,
               (const float*)nullptr, (const void*)nullptr);
    // 3. attention -> Ob
    launch_pdl(attn_kernel, dim3(Bb*Hh), dim3(256), (size_t)ATTN_SMEM,
               (const __half*)QKVb, (__half*)Ob);
    // 4. X1h = fp16(x + Ob @ Wpt^T + bp)
    launch_pdl(gemm_tc<5, true, false>, dim3(Dd/128, ROWS/128), dim3(256), (size_t)GEMM_SMEM,
               (const __half*)Ob, (const __half*)Wpt, (void*)X1h, Dd, Dd,
               (const float*)bp, (const void*)x);
    // 5. LN2 -> Hb (fp16 in)
    launch_pdl(ln2_kernel, dim3(ROWS/8), dim3(256), (size_t)0,
               (const __half*)X1h, (const float*)g2, (const float*)be2, (__half*)Hb);
    // 6. A1 = relu(Hb @ W1t^T + b1)
    launch_pdl(gemm_tc<3, true, false>, dim3(DFF/128, ROWS/128), dim3(256), (size_t)GEMM_SMEM,
               (const __half*)Hb, (const __half*)W1t, (void*)A1b, DFF, Dd,
               (const float*)b1, (const void*)nullptr);
    // 7. out = X1h + A1 @ W2t^T + b2 (fp32 out, fp16 resid)
    launch_pdl(gemm_tc<5, false, true>, dim3(Dd/128, ROWS/128), dim3(256), (size_t)GEMM_SMEM,
               (const __half*)A1b, (const __half*)W2t, (void*)out, Dd, DFF,
               (const float*)b2, (const void*)X1h);
}

// round 14
// speedup vs baseline: 1.0377x; 1.0377x over previous
#include <cuda_runtime.h>
#include <cuda_fp16.h>
#include <cstdint>

#define Bb   128
#define Tt   256
#define Dd   384
#define Hh   6
#define HD   64
#define ROWS (Bb*Tt)          // 32768
#define DFF  (4*Dd)           // 1536

// ------------------------- scratch (device globals) -------------------------
__device__ __half g_Hb[ROWS * Dd];
__device__ __half g_Xh[ROWS * Dd];        // fp16 copy of x (proj residual)
__device__ __half g_QKVb[ROWS * 3 * Dd];
__device__ __half g_Ob[ROWS * Dd];
__device__ __half g_X1h[ROWS * Dd];       // x + attn proj, fp16
__device__ __half g_A1b[ROWS * DFF];
__device__ __half g_WQKVt[3*Dd * Dd];     // [1152,384] K-major
__device__ __half g_Wpt[Dd * Dd];
__device__ __half g_W1t[DFF * Dd];
__device__ __half g_W2t[Dd * DFF];

// ------------------------------ helpers ------------------------------
__device__ __forceinline__ uint32_t smem_u32(const void* p) {
    uint32_t a;
    asm("{ .reg .u64 t; cvta.to.shared.u64 t, %1; cvt.u32.u64 %0, t; }" : "=r"(a) : "l"(p));
    return a;
}

#define GDC_WAIT()  asm volatile("griddepcontrol.wait;" ::: "memory")
#define GDC_TRIG()  asm volatile("griddepcontrol.launch_dependents;" ::: "memory")

#define CPA(dst, src) \
    asm volatile("cp.async.cg.shared.global [%0], [%1], 16;" :: "r"(dst), "l"(src))
#define CPA_COMMIT() asm volatile("cp.async.commit_group;" ::: "memory")

#define LDSM4(r0, r1, r2, r3, a) \
    asm volatile("ldmatrix.sync.aligned.m8n8.x4.shared.b16 {%0,%1,%2,%3}, [%4];" \
                 : "=r"(r0), "=r"(r1), "=r"(r2), "=r"(r3) : "r"(a))
#define LDSM4T(r0, r1, r2, r3, a) \
    asm volatile("ldmatrix.sync.aligned.m8n8.x4.trans.shared.b16 {%0,%1,%2,%3}, [%4];" \
                 : "=r"(r0), "=r"(r1), "=r"(r2), "=r"(r3) : "r"(a))

// fp16 inputs, fp32 accumulators (attention)
#define MMA16816F(d, a0, a1, a2, a3, b0, b1) \
    asm volatile("mma.sync.aligned.m16n8k16.row.col.f32.f16.f16.f32 " \
                 "{%0,%1,%2,%3}, {%4,%5,%6,%7}, {%8,%9}, {%0,%1,%2,%3};" \
                 : "+f"((d)[0]), "+f"((d)[1]), "+f"((d)[2]), "+f"((d)[3]) \
                 : "r"(a0), "r"(a1), "r"(a2), "r"(a3), "r"(b0), "r"(b1))

// fp16 inputs, fp16 accumulators (GEMMs)
#define MMA16816H(d, a0, a1, a2, a3, b0, b1) \
    asm volatile("mma.sync.aligned.m16n8k16.row.col.f16.f16.f16.f16 " \
                 "{%0,%1}, {%2,%3,%4,%5}, {%6,%7}, {%0,%1};" \
                 : "+r"((d)[0]), "+r"((d)[1]) \
                 : "r"(a0), "r"(a1), "r"(a2), "r"(a3), "r"(b0), "r"(b1))

__device__ __forceinline__ uint32_t pkhf(float a, float b) {
    __half2 t = __floats2half2_rn(a, b);
    return *reinterpret_cast<uint32_t*>(&t);
}
#define PKH2(d, a, b) \
    asm("cvt.rn.f16x2.f32 %0, %2, %1;" : "=r"(d) : "f"(a), "f"(b))
#define EX2H2(r) asm("ex2.approx.f16x2 %0, %0;" : "+r"(r))

// ------------------- fused LN1 + x->fp16 + weight pack -------------------
#define LN_BLKS (ROWS/8)
#define PACK_TOTAL (2*Dd*Dd + 2*Dd*DFF)
#define PK_BLKS ((PACK_TOTAL + 255)/256)

__global__ void __launch_bounds__(256) ln1_pack(
    const float* __restrict__ x, const float* __restrict__ g, const float* __restrict__ be,
    __half* __restrict__ out, __half* __restrict__ xh,
    const float* __restrict__ Wq, const float* __restrict__ Wk, const float* __restrict__ Wv,
    const float* __restrict__ Wp, const float* __restrict__ W1, const float* __restrict__ W2,
    __half* __restrict__ WQKVt, __half* __restrict__ Wpt,
    __half* __restrict__ W1t,   __half* __restrict__ W2t)
{
    const int tid = threadIdx.x;
    if (blockIdx.x < LN_BLKS) {
        const int w = tid >> 5, l = tid & 31;
        const int row = blockIdx.x * 8 + w;
        const float* xr = x + (size_t)row * Dd;
        float4 v[3];
#pragma unroll
        for (int i = 0; i < 3; i++) v[i] = *(const float4*)(xr + i * 128 + l * 4);
        // fp16 copy of x for proj residual
        __half* xhrow = xh + (size_t)row * Dd;
#pragma unroll
        for (int i = 0; i < 3; i++) {
            const int c = i * 128 + l * 4;
            uint2 o;
            o.x = pkhf(v[i].x, v[i].y);
            o.y = pkhf(v[i].z, v[i].w);
            *(uint2*)(xhrow + c) = o;
        }
        float s = 0.f, sq = 0.f;
#pragma unroll
        for (int i = 0; i < 3; i++) {
            s  += v[i].x + v[i].y + v[i].z + v[i].w;
            sq += v[i].x*v[i].x + v[i].y*v[i].y + v[i].z*v[i].z + v[i].w*v[i].w;
        }
#pragma unroll
        for (int o = 16; o; o >>= 1) {
            s  += __shfl_xor_sync(0xffffffffu, s,  o);
            sq += __shfl_xor_sync(0xffffffffu, sq, o);
        }
        const float mean = s * (1.0f / Dd);
        const float var  = sq * (1.0f / Dd) - mean * mean;
        const float rstd = rsqrtf(var + 1e-5f);
        __half* orow = out + (size_t)row * Dd;
#pragma unroll
        for (int i = 0; i < 3; i++) {
            const int c = i * 128 + l * 4;
            const float4 gg = *(const float4*)(g + c);
            const float4 bb = *(const float4*)(be + c);
            uint2 o;
            o.x = pkhf((v[i].x - mean) * rstd * gg.x + bb.x,
                       (v[i].y - mean) * rstd * gg.y + bb.y);
            o.y = pkhf((v[i].z - mean) * rstd * gg.z + bb.z,
                       (v[i].w - mean) * rstd * gg.w + bb.w);
            *(uint2*)(orow + c) = o;
        }
    } else {
        int idx = (blockIdx.x - LN_BLKS) * 256 + tid;
        if (idx >= PACK_TOTAL) return;
        const int n1 = Dd * Dd, n2 = 2 * Dd * Dd, n3 = 2 * Dd * Dd + Dd * DFF;
        if (idx < n1) {
            int d = idx / Dd, col = idx % Dd;
            int h = col >> 6, k = col & 63;
            int src = h * (Dd * HD) + d * HD + k;
            WQKVt[(size_t)col * Dd + d]          = __float2half_rn(Wq[src]);
            WQKVt[(size_t)(Dd + col) * Dd + d]   = __float2half_rn(Wk[src]);
            WQKVt[(size_t)(2*Dd + col) * Dd + d] = __float2half_rn(Wv[src]);
        } else if (idx < n2) {
            int i = idx - n1;
            int n = i / Dd, d = i % Dd;
            Wpt[(size_t)n * Dd + d] = __float2half_rn(Wp[(size_t)d * Dd + n]);
        } else if (idx < n3) {
            int i = idx - n2;
            int n = i / Dd, d = i % Dd;
            W1t[(size_t)n * Dd + d] = __float2half_rn(W1[(size_t)d * DFF + n]);
        } else {
            int i = idx - n3;
            int n = i / DFF, d = i % DFF;
            W2t[(size_t)n * DFF + d] = __float2half_rn(W2[(size_t)d * Dd + n]);
        }
    }
}

// ------------------------------ LayerNorm (LN2, fp16 in, PDL) ------------------------------
__global__ void __launch_bounds__(256) ln2_kernel(const __half* __restrict__ x,
                                                  const float* __restrict__ g,
                                                  const float* __restrict__ be,
                                                  __half* __restrict__ out)
{
    GDC_WAIT();
    GDC_TRIG();
    const int w = threadIdx.x >> 5, l = threadIdx.x & 31;
    const int row = blockIdx.x * 8 + w;
    const __half* xr = x + (size_t)row * Dd;
    float4 v[3];
#pragma unroll
    for (int i = 0; i < 3; i++) {
        uint2 raw = *(const uint2*)(xr + i * 128 + l * 4);
        float2 f01 = __half22float2(*reinterpret_cast<__half2*>(&raw.x));
        float2 f23 = __half22float2(*reinterpret_cast<__half2*>(&raw.y));
        v[i] = make_float4(f01.x, f01.y, f23.x, f23.y);
    }
    float s = 0.f, sq = 0.f;
#pragma unroll
    for (int i = 0; i < 3; i++) {
        s  += v[i].x + v[i].y + v[i].z + v[i].w;
        sq += v[i].x*v[i].x + v[i].y*v[i].y + v[i].z*v[i].z + v[i].w*v[i].w;
    }
#pragma unroll
    for (int o = 16; o; o >>= 1) {
        s  += __shfl_xor_sync(0xffffffffu, s,  o);
        sq += __shfl_xor_sync(0xffffffffu, sq, o);
    }
    const float mean = s * (1.0f / Dd);
    const float var  = sq * (1.0f / Dd) - mean * mean;
    const float rstd = rsqrtf(var + 1e-5f);
    __half* orow = out + (size_t)row * Dd;
#pragma unroll
    for (int i = 0; i < 3; i++) {
        const int c = i * 128 + l * 4;
        const float4 gg = *(const float4*)(g + c);
        const float4 bb = *(const float4*)(be + c);
        uint2 o;
        o.x = pkhf((v[i].x - mean) * rstd * gg.x + bb.x,
                   (v[i].y - mean) * rstd * gg.y + bb.y);
        o.y = pkhf((v[i].z - mean) * rstd * gg.z + bb.z,
                   (v[i].w - mean) * rstd * gg.w + bb.w);
        *(uint2*)(orow + c) = o;
    }
}

// ------------------------------- fp16 HMMA GEMM (round-12 proven) -------------------------------
// 128x128 CTA tile, 4 warps (warp tile 64x64), 3-stage pipeline, 3 CTAs/SM.
// EPI bits: 1=bias 2=relu 4=resid. RESHF: resid fp16. OHF: output fp16.
#define GOP_B   10240
#define GSTG_B  (2*GOP_B)
#define GNST    3
#define GEMM_SMEM (GNST*GSTG_B)  // 61440

template <int EPI, bool OHF, bool RESHF>
__global__ void __launch_bounds__(128, 3)
gemm_tc(const __half* __restrict__ A, const __half* __restrict__ B,
        void* __restrict__ Cv, int N, int K,
        const float* __restrict__ bias, const void* __restrict__ resid)
{
    extern __shared__ char smg[];
    const uint32_t s0 = smem_u32(smg);
    const int tid = threadIdx.x, w = tid >> 5, l = tid & 31;
    const int bn = blockIdx.x * 128, bm = blockIdx.y * 128;
    const int wm = w & 1, wn = w >> 1;

    const int lc = tid & 3, lr = tid >> 2;
    const __half* Ag = A + (size_t)(bm + lr) * K + lc * 8;
    const __half* Bg = B + (size_t)(bn + lr) * K + lc * 8;
    const uint32_t stoff = (uint32_t)(lr * 40 + lc * 8) * 2;

    uint32_t hacc[4][8][2];
#pragma unroll
    for (int i = 0; i < 4; i++)
#pragma unroll
        for (int j = 0; j < 8; j++) { hacc[i][j][0] = 0u; hacc[i][j][1] = 0u; }

    const int S = K / 32;

#define GA_ISSUE(p) do { \
    const uint32_t dst = s0 + ((p) % GNST) * GSTG_B; \
    const __half* ag = Ag + (p) * 32; \
    CPA(dst + stoff,          ag); \
    CPA(dst + stoff + 2560,   ag + (size_t)32 * K); \
    CPA(dst + stoff + 5120,   ag + (size_t)64 * K); \
    CPA(dst + stoff + 7680,   ag + (size_t)96 * K); \
} while (0)
#define GB_ISSUE(p) do { \
    const uint32_t dst = s0 + ((p) % GNST) * GSTG_B + GOP_B; \
    const __half* bg = Bg + (p) * 32; \
    CPA(dst + stoff,          bg); \
    CPA(dst + stoff + 2560,   bg + (size_t)32 * K); \
    CPA(dst + stoff + 5120,   bg + (size_t)64 * K); \
    CPA(dst + stoff + 7680,   bg + (size_t)96 * K); \
} while (0)

    GB_ISSUE(0); CPA_COMMIT();
    GB_ISSUE(1); CPA_COMMIT();
    GDC_WAIT();
    GA_ISSUE(0); CPA_COMMIT();
    GA_ISSUE(1); CPA_COMMIT();

    const int arow = ((l >> 3) & 1) * 8 + (l & 7);
    const uint32_t aBase = s0 + (uint32_t)((wm * 64 + arow) * 80) + (l >> 4) * 16;
    const int brow = (l >> 4) * 8 + (l & 7);
    const uint32_t bBase = s0 + GOP_B + (uint32_t)((wn * 64 + brow) * 80) + ((l >> 3) & 1) * 16;

    uint32_t af[4][4], bf[8][2];

#define G_LOADFRAG(ab, bb, ks) do { \
    _Pragma("unroll") \
    for (int mt = 0; mt < 4; mt++) \
        LDSM4(af[mt][0], af[mt][1], af[mt][2], af[mt][3], \
              (ab) + mt * 1280 + (ks) * 32); \
    _Pragma("unroll") \
    for (int pr = 0; pr < 4; pr++) { \
        uint32_t t0, t1, t2, t3; \
        LDSM4(t0, t1, t2, t3, (bb) + pr * 1280 + (ks) * 32); \
        bf[2*pr][0] = t0; bf[2*pr][1] = t1; \
        bf[2*pr+1][0] = t2; bf[2*pr+1][1] = t3; \
    } } while (0)

#define G_MMA() do { \
    _Pragma("unroll") \
    for (int mt = 0; mt < 4; mt++) \
        _Pragma("unroll") \
        for (int nt = 0; nt < 8; nt++) \
            MMA16816H(hacc[mt][nt], af[mt][0], af[mt][1], \
                      af[mt][2], af[mt][3], bf[nt][0], bf[nt][1]); \
    } while (0)

    for (int s = 0; s < S; s++) {
        asm volatile("cp.async.wait_group 1;" ::: "memory");
        __syncthreads();
        if (s + 2 < S) { GA_ISSUE(s + 2); GB_ISSUE(s + 2); }
        CPA_COMMIT();

        const uint32_t off = (uint32_t)((s % GNST) * GSTG_B);
        G_LOADFRAG(aBase + off, bBase + off, 0);
        G_MMA();
        G_LOADFRAG(aBase + off, bBase + off, 1);
        G_MMA();
    }
#undef GA_ISSUE
#undef GB_ISSUE
#undef G_LOADFRAG
#undef G_MMA

    GDC_TRIG();

    const int qr = l >> 2, qc = (l & 3) * 2;
#pragma unroll
    for (int mt = 0; mt < 4; mt++) {
#pragma unroll
        for (int half = 0; half < 2; half++) {
            const int r = bm + wm * 64 + mt * 16 + qr + half * 8;
#pragma unroll
            for (int nt = 0; nt < 8; nt++) {
                const int c = bn + wn * 64 + nt * 8 + qc;
                float2 vv = __half22float2(
                    *reinterpret_cast<__half2*>(&hacc[mt][nt][half]));
                float v0 = vv.x, v1 = vv.y;
                if (EPI & 1) { v0 += bias[c]; v1 += bias[c + 1]; }
                if (EPI & 2) { v0 = fmaxf(v0, 0.0f); v1 = fmaxf(v1, 0.0f); }
                if (EPI & 4) {
                    if (RESHF) {
                        uint32_t rr = *(const uint32_t*)((const __half*)resid + (size_t)r * N + c);
                        float2 rf = __half22float2(*reinterpret_cast<__half2*>(&rr));
                        v0 += rf.x; v1 += rf.y;
                    } else {
                        float2 rv = *(const float2*)((const float*)resid + (size_t)r * N + c);
                        v0 += rv.x; v1 += rv.y;
                    }
                }
                if (OHF) {
                    *(uint32_t*)((__half*)Cv + (size_t)r * N + c) = pkhf(v0, v1);
                } else {
                    *(float2*)((float*)Cv + (size_t)r * N + c) = make_float2(v0, v1);
                }
            }
        }
    }
}

// --------------------------- Attention (HMMA flash, f16x2 softmax) ---------------------------
#define KV_PITCH 72

__global__ void __launch_bounds__(256, 3) attn_kernel(const __half* __restrict__ QKV,
                                                      __half* __restrict__ O)
{
    GDC_WAIT();
    extern __shared__ __align__(16) __half smkv[];
    const uint32_t sK = smem_u32(smkv);
    const uint32_t sV = sK + Tt * KV_PITCH * 2;
    const int bh = blockIdx.x;
    const int b = bh / Hh, h = bh % Hh;
    const int tid = threadIdx.x;
    const __half* base = QKV + (size_t)b * Tt * (3*Dd) + h * HD;

    for (int idx = tid; idx < 2 * 2048; idx += 256) {
        int half = idx >> 11, i = idx & 2047;
        int row = i >> 3, c8 = i & 7;
        const uint4 v = *(const uint4*)(base + (size_t)row * (3*Dd) + (half + 1) * Dd + c8 * 8);
        *(uint4*)((char*)smkv + (half ? (size_t)Tt * KV_PITCH * 2 : 0)
                  + row * (KV_PITCH*2) + c8 * 16) = v;
    }
    __syncthreads();

    const int w = tid >> 5, l = tid & 31;
    const int qr = l >> 2, qc = l & 3;

    const uint32_t kAddr = sK + (uint32_t)(((l >> 4) * 8 + (l & 7)) * (KV_PITCH*2))
                               + ((l >> 3) & 1) * 16;
    const uint32_t vAddr = sV + (uint32_t)((((l >> 3) & 1) * 8 + (l & 7)) * (KV_PITCH*2))
                               + ((l >> 4) & 1) * 16;

    const float sc2 = rsqrtf((float)Dd) * 1.4426950408889634f;

#pragma unroll
    for (int job = 0; job < 2; job++) {
        const int bt = job ? 16 * (15 - w) : 16 * w;
        const int nch = job ? (16 - w) : (w + 1);

        const __half* Qrow = base + (size_t)bt * (3*Dd);
        uint32_t qa[4][4];
#pragma unroll
        for (int kc = 0; kc < 4; kc++) {
            int k0 = kc * 16 + qc * 2;
            qa[kc][0] = *(const uint32_t*)(Qrow + (size_t)qr * (3*Dd) + k0);
            qa[kc][1] = *(const uint32_t*)(Qrow + (size_t)(qr + 8) * (3*Dd) + k0);
            qa[kc][2] = *(const uint32_t*)(Qrow + (size_t)qr * (3*Dd) + k0 + 8);
            qa[kc][3] = *(const uint32_t*)(Qrow + (size_t)(qr + 8) * (3*Dd) + k0 + 8);
        }

        float oacc[8][4];
#pragma unroll
        for (int i = 0; i < 8; i++)
#pragma unroll
            for (int j = 0; j < 4; j++) oacc[i][j] = 0.0f;
        float l0 = 0.0f, l1 = 0.0f;

        for (int c = 0; c < nch; c++) {
            const uint32_t kRow = kAddr + c * 16 * (KV_PITCH*2);
            float s[2][4];
#pragma unroll
            for (int nt = 0; nt < 2; nt++)
#pragma unroll
                for (int j = 0; j < 4; j++) s[nt][j] = 0.0f;
#pragma unroll
            for (int kc = 0; kc < 4; kc++) {
                uint32_t k0, k1, k2, k3;
                LDSM4(k0, k1, k2, k3, kRow + kc * 32);
                MMA16816F(s[0], qa[kc][0], qa[kc][1], qa[kc][2], qa[kc][3], k0, k1);
                MMA16816F(s[1], qa[kc][0], qa[kc][1], qa[kc][2], qa[kc][3], k2, k3);
            }
            const bool maskc = (c == nch - 1);
#pragma unroll
            for (int nt = 0; nt < 2; nt++)
#pragma unroll
                for (int j = 0; j < 4; j++) {
                    float sv = fminf(s[nt][j] * sc2, 10.0f);
                    if (maskc) {
                        int trow = bt + qr + 8 * (j >> 1);
                        int scol = 16 * c + 8 * nt + 2 * qc + (j & 1);
                        if (scol > trow) sv = -60000.0f;
                    }
                    s[nt][j] = sv;
                }
            uint32_t pa0, pa1, pa2, pa3;
            PKH2(pa0, s[0][0], s[0][1]);
            PKH2(pa1, s[0][2], s[0][3]);
            PKH2(pa2, s[1][0], s[1][1]);
            PKH2(pa3, s[1][2], s[1][3]);
            EX2H2(pa0); EX2H2(pa1); EX2H2(pa2); EX2H2(pa3);
            {
                __half2 h0 = __hadd2(*reinterpret_cast<__half2*>(&pa0),
                                     *reinterpret_cast<__half2*>(&pa2));
                __half2 h1 = __hadd2(*reinterpret_cast<__half2*>(&pa1),
                                     *reinterpret_cast<__half2*>(&pa3));
                float2 f0 = __half22float2(h0), f1 = __half22float2(h1);
                l0 += f0.x + f0.y;
                l1 += f1.x + f1.y;
            }

            const uint32_t vRow = vAddr + c * 16 * (KV_PITCH*2);
#pragma unroll
            for (int g = 0; g < 4; g++) {
                uint32_t v0, v1, v2, v3;
                LDSM4T(v0, v1, v2, v3, vRow + g * 32);
                MMA16816F(oacc[2*g],     pa0, pa1, pa2, pa3, v0, v1);
                MMA16816F(oacc[2*g + 1], pa0, pa1, pa2, pa3, v2, v3);
            }
        }

        if (job == 1) GDC_TRIG();

        l0 += __shfl_xor_sync(0xffffffffu, l0, 1);
        l0 += __shfl_xor_sync(0xffffffffu, l0, 2);
        l1 += __shfl_xor_sync(0xffffffffu, l1, 1);
        l1 += __shfl_xor_sync(0xffffffffu, l1, 2);
        const float i0 = 1.0f / l0, i1 = 1.0f / l1;

        __half* Orow = O + ((size_t)b * Tt + bt) * Dd + h * HD;
#pragma unroll
        for (int dt = 0; dt < 8; dt++) {
            int col = dt * 8 + qc * 2;
            *(uint32_t*)(Orow + (size_t)qr * Dd + col) =
                pkhf(oacc[dt][0] * i0, oacc[dt][1] * i0);
            *(uint32_t*)(Orow + (size_t)(qr + 8) * Dd + col) =
                pkhf(oacc[dt][2] * i1, oacc[dt][3] * i1);
        }
    }
}

// ------------------------------- launch -------------------------------
template <typename F, typename... Args>
static void launch_pdl(F func, dim3 grid, dim3 block, size_t smem, Args... args)
{
    cudaLaunchConfig_t cfg = {};
    cfg.gridDim = grid; cfg.blockDim = block;
    cfg.dynamicSmemBytes = smem; cfg.stream = 0;
    cudaLaunchAttribute at[1];
    at[0].id = cudaLaunchAttributeProgrammaticStreamSerialization;
    at[0].val.programmaticStreamSerializationAllowed = 1;
    cfg.attrs = at; cfg.numAttrs = 1;
    cudaLaunchKernelEx(&cfg, func, args...);
}

extern "C" void kernel_launch(void* const* d_in, const int* in_sizes, int n_in,
                              void* d_out, int out_size)
{
    const float* x   = (const float*)d_in[0];
    const float* Wq  = (const float*)d_in[1];
    const float* Wk  = (const float*)d_in[2];
    const float* Wv  = (const float*)d_in[3];
    const float* Wp  = (const float*)d_in[4];
    const float* bp  = (const float*)d_in[5];
    const float* W1  = (const float*)d_in[6];
    const float* b1  = (const float*)d_in[7];
    const float* W2  = (const float*)d_in[8];
    const float* b2  = (const float*)d_in[9];
    const float* g1  = (const float*)d_in[10];
    const float* be1 = (const float*)d_in[11];
    const float* g2  = (const float*)d_in[12];
    const float* be2 = (const float*)d_in[13];
    float* out = (float*)d_out;

    __half *Hb, *Xh, *QKVb, *Ob, *X1h, *A1b, *WQKVt, *Wpt, *W1t, *W2t;
    cudaGetSymbolAddress((void**)&Hb,    g_Hb);
    cudaGetSymbolAddress((void**)&Xh,    g_Xh);
    cudaGetSymbolAddress((void**)&QKVb,  g_QKVb);
    cudaGetSymbolAddress((void**)&Ob,    g_Ob);
    cudaGetSymbolAddress((void**)&X1h,   g_X1h);
    cudaGetSymbolAddress((void**)&A1b,   g_A1b);
    cudaGetSymbolAddress((void**)&WQKVt, g_WQKVt);
    cudaGetSymbolAddress((void**)&Wpt,   g_Wpt);
    cudaGetSymbolAddress((void**)&W1t,   g_W1t);
    cudaGetSymbolAddress((void**)&W2t,   g_W2t);

    const int ATTN_SMEM = Tt * KV_PITCH * 2 * 2;  // 73728
    cudaFuncSetAttribute(attn_kernel, cudaFuncAttributeMaxDynamicSharedMemorySize, ATTN_SMEM);
    cudaFuncSetAttribute(gemm_tc<0, true, false>, cudaFuncAttributeMaxDynamicSharedMemorySize, GEMM_SMEM);
    cudaFuncSetAttribute(gemm_tc<5, true, true>,  cudaFuncAttributeMaxDynamicSharedMemorySize, GEMM_SMEM);
    cudaFuncSetAttribute(gemm_tc<3, true, false>, cudaFuncAttributeMaxDynamicSharedMemorySize, GEMM_SMEM);
    cudaFuncSetAttribute(gemm_tc<5, false, true>, cudaFuncAttributeMaxDynamicSharedMemorySize, GEMM_SMEM);

    // 1. LN1 + x->fp16 + weight pack
    ln1_pack<<<LN_BLKS + PK_BLKS, 256>>>(x, g1, be1, Hb, Xh,
                                         Wq, Wk, Wv, Wp, W1, W2,
                                         WQKVt, Wpt, W1t, W2t);
    // 2. QKV = Hb @ WQKVt^T
    launch_pdl(gemm_tc<0, true, false>, dim3((3*Dd)/128, ROWS/128), dim3(128), (size_t)GEMM_SMEM,
               (const __half*)Hb, (const __half*)WQKVt, (void*)QKVb, 3*Dd, Dd,
               (const float*)nullptr, (const void*)nullptr);
    // 3. attention -> Ob
    launch_pdl(attn_kernel, dim3(Bb*Hh), dim3(256), (size_t)ATTN_SMEM,
               (const __half*)QKVb, (__half*)Ob);
    // 4. X1h = fp16(xh + Ob @ Wpt^T + bp)  (fp16 resid)
    launch_pdl(gemm_tc<5, true, true>, dim3(Dd/128, ROWS/128), dim3(128), (size_t)GEMM_SMEM,
               (const __half*)Ob, (const __half*)Wpt, (void*)X1h, Dd, Dd,
               (const float*)bp, (const void*)Xh);
    // 5. LN2 -> Hb (fp16 in)
    launch_pdl(ln2_kernel, dim3(ROWS/8), dim3(256), (size_t)0,
               (const __half*)X1h, (const float*)g2, (const float*)be2, (__half*)Hb);
    // 6. A1 = relu(Hb @ W1t^T + b1)
    launch_pdl(gemm_tc<3, true, false>, dim3(DFF/128, ROWS/128), dim3(128), (size_t)GEMM_SMEM,
               (const __half*)Hb, (const __half*)W1t, (void*)A1b, DFF, Dd,
               (const float*)b1, (const void*)nullptr);
    // 7. out = X1h + A1 @ W2t^T + b2 (fp32 out, fp16 resid)
    launch_pdl(gemm_tc<5, false, true>, dim3(Dd/128, ROWS/128), dim3(128), (size_t)GEMM_SMEM,
               (const __half*)A1b, (const __half*)W2t, (void*)out, Dd, DFF,
               (const float*)b2, (const void*)X1h);
}

// round 15
// speedup vs baseline: 1.0385x; 1.0008x over previous
#include <cuda_runtime.h>
#include <cuda_fp16.h>
#include <cstdint>

#define Bb   128
#define Tt   256
#define Dd   384
#define Hh   6
#define HD   64
#define ROWS (Bb*Tt)          // 32768
#define DFF  (4*Dd)           // 1536

// ------------------------- scratch (device globals) -------------------------
__device__ __half g_Hb[ROWS * Dd];
__device__ __half g_Xh[ROWS * Dd];        // fp16 copy of x (proj residual)
__device__ __half g_QKVb[ROWS * 3 * Dd];
__device__ __half g_Ob[ROWS * Dd];
__device__ __half g_X1h[ROWS * Dd];       // x + attn proj, fp16
__device__ __half g_A1b[ROWS * DFF];
__device__ __half g_WQKVt[3*Dd * Dd];     // [1152,384] K-major
__device__ __half g_Wpt[Dd * Dd];
__device__ __half g_W1t[DFF * Dd];
__device__ __half g_W2t[Dd * DFF];

// ------------------------------ helpers ------------------------------
__device__ __forceinline__ uint32_t smem_u32(const void* p) {
    uint32_t a;
    asm("{ .reg .u64 t; cvta.to.shared.u64 t, %1; cvt.u32.u64 %0, t; }" : "=r"(a) : "l"(p));
    return a;
}

#define GDC_WAIT()  asm volatile("griddepcontrol.wait;" ::: "memory")
#define GDC_TRIG()  asm volatile("griddepcontrol.launch_dependents;" ::: "memory")

#define CPA(dst, src) \
    asm volatile("cp.async.cg.shared.global [%0], [%1], 16;" :: "r"(dst), "l"(src))
#define CPA_COMMIT() asm volatile("cp.async.commit_group;" ::: "memory")

#define LDSM4(r0, r1, r2, r3, a) \
    asm volatile("ldmatrix.sync.aligned.m8n8.x4.shared.b16 {%0,%1,%2,%3}, [%4];" \
                 : "=r"(r0), "=r"(r1), "=r"(r2), "=r"(r3) : "r"(a))
#define LDSM4T(r0, r1, r2, r3, a) \
    asm volatile("ldmatrix.sync.aligned.m8n8.x4.trans.shared.b16 {%0,%1,%2,%3}, [%4];" \
                 : "=r"(r0), "=r"(r1), "=r"(r2), "=r"(r3) : "r"(a))

// fp16 inputs, fp32 accumulators (attention)
#define MMA16816F(d, a0, a1, a2, a3, b0, b1) \
    asm volatile("mma.sync.aligned.m16n8k16.row.col.f32.f16.f16.f32 " \
                 "{%0,%1,%2,%3}, {%4,%5,%6,%7}, {%8,%9}, {%0,%1,%2,%3};" \
                 : "+f"((d)[0]), "+f"((d)[1]), "+f"((d)[2]), "+f"((d)[3]) \
                 : "r"(a0), "r"(a1), "r"(a2), "r"(a3), "r"(b0), "r"(b1))

// fp16 inputs, fp16 accumulators (GEMMs)
#define MMA16816H(d, a0, a1, a2, a3, b0, b1) \
    asm volatile("mma.sync.aligned.m16n8k16.row.col.f16.f16.f16.f16 " \
                 "{%0,%1}, {%2,%3,%4,%5}, {%6,%7}, {%0,%1};" \
                 : "+r"((d)[0]), "+r"((d)[1]) \
                 : "r"(a0), "r"(a1), "r"(a2), "r"(a3), "r"(b0), "r"(b1))

__device__ __forceinline__ uint32_t pkhf(float a, float b) {
    __half2 t = __floats2half2_rn(a, b);
    return *reinterpret_cast<uint32_t*>(&t);
}
#define PKH2(d, a, b) \
    asm("cvt.rn.f16x2.f32 %0, %2, %1;" : "=r"(d) : "f"(a), "f"(b))
#define EX2H2(r) asm("ex2.approx.f16x2 %0, %0;" : "+r"(r))

// ------------------- fused LN1 + x->fp16 + weight pack -------------------
#define LN_BLKS (ROWS/8)
#define PACK_TOTAL (2*Dd*Dd + 2*Dd*DFF)
#define PK_BLKS ((PACK_TOTAL + 255)/256)

__global__ void __launch_bounds__(256) ln1_pack(
    const float* __restrict__ x, const float* __restrict__ g, const float* __restrict__ be,
    __half* __restrict__ out, __half* __restrict__ xh,
    const float* __restrict__ Wq, const float* __restrict__ Wk, const float* __restrict__ Wv,
    const float* __restrict__ Wp, const float* __restrict__ W1, const float* __restrict__ W2,
    __half* __restrict__ WQKVt, __half* __restrict__ Wpt,
    __half* __restrict__ W1t,   __half* __restrict__ W2t)
{
    const int tid = threadIdx.x;
    if (blockIdx.x < LN_BLKS) {
        const int w = tid >> 5, l = tid & 31;
        const int row = blockIdx.x * 8 + w;
        const float* xr = x + (size_t)row * Dd;
        float4 v[3];
#pragma unroll
        for (int i = 0; i < 3; i++) v[i] = *(const float4*)(xr + i * 128 + l * 4);
        __half* xhrow = xh + (size_t)row * Dd;
#pragma unroll
        for (int i = 0; i < 3; i++) {
            const int c = i * 128 + l * 4;
            uint2 o;
            o.x = pkhf(v[i].x, v[i].y);
            o.y = pkhf(v[i].z, v[i].w);
            *(uint2*)(xhrow + c) = o;
        }
        float s = 0.f, sq = 0.f;
#pragma unroll
        for (int i = 0; i < 3; i++) {
            s  += v[i].x + v[i].y + v[i].z + v[i].w;
            sq += v[i].x*v[i].x + v[i].y*v[i].y + v[i].z*v[i].z + v[i].w*v[i].w;
        }
#pragma unroll
        for (int o = 16; o; o >>= 1) {
            s  += __shfl_xor_sync(0xffffffffu, s,  o);
            sq += __shfl_xor_sync(0xffffffffu, sq, o);
        }
        const float mean = s * (1.0f / Dd);
        const float var  = sq * (1.0f / Dd) - mean * mean;
        const float rstd = rsqrtf(var + 1e-5f);
        __half* orow = out + (size_t)row * Dd;
#pragma unroll
        for (int i = 0; i < 3; i++) {
            const int c = i * 128 + l * 4;
            const float4 gg = *(const float4*)(g + c);
            const float4 bb = *(const float4*)(be + c);
            uint2 o;
            o.x = pkhf((v[i].x - mean) * rstd * gg.x + bb.x,
                       (v[i].y - mean) * rstd * gg.y + bb.y);
            o.y = pkhf((v[i].z - mean) * rstd * gg.z + bb.z,
                       (v[i].w - mean) * rstd * gg.w + bb.w);
            *(uint2*)(orow + c) = o;
        }
    } else {
        int idx = (blockIdx.x - LN_BLKS) * 256 + tid;
        if (idx >= PACK_TOTAL) return;
        const int n1 = Dd * Dd, n2 = 2 * Dd * Dd, n3 = 2 * Dd * Dd + Dd * DFF;
        if (idx < n1) {
            int d = idx / Dd, col = idx % Dd;
            int h = col >> 6, k = col & 63;
            int src = h * (Dd * HD) + d * HD + k;
            WQKVt[(size_t)col * Dd + d]          = __float2half_rn(Wq[src]);
            WQKVt[(size_t)(Dd + col) * Dd + d]   = __float2half_rn(Wk[src]);
            WQKVt[(size_t)(2*Dd + col) * Dd + d] = __float2half_rn(Wv[src]);
        } else if (idx < n2) {
            int i = idx - n1;
            int n = i / Dd, d = i % Dd;
            Wpt[(size_t)n * Dd + d] = __float2half_rn(Wp[(size_t)d * Dd + n]);
        } else if (idx < n3) {
            int i = idx - n2;
            int n = i / Dd, d = i % Dd;
            W1t[(size_t)n * Dd + d] = __float2half_rn(W1[(size_t)d * DFF + n]);
        } else {
            int i = idx - n3;
            int n = i / DFF, d = i % DFF;
            W2t[(size_t)n * DFF + d] = __float2half_rn(W2[(size_t)d * Dd + n]);
        }
    }
}

// ------------------------------ LayerNorm (LN2, fp16 in, PDL) ------------------------------
__global__ void __launch_bounds__(256) ln2_kernel(const __half* __restrict__ x,
                                                  const float* __restrict__ g,
                                                  const float* __restrict__ be,
                                                  __half* __restrict__ out)
{
    GDC_WAIT();
    GDC_TRIG();
    const int w = threadIdx.x >> 5, l = threadIdx.x & 31;
    const int row = blockIdx.x * 8 + w;
    const __half* xr = x + (size_t)row * Dd;
    float4 v[3];
#pragma unroll
    for (int i = 0; i < 3; i++) {
        uint2 raw = *(const uint2*)(xr + i * 128 + l * 4);
        float2 f01 = __half22float2(*reinterpret_cast<__half2*>(&raw.x));
        float2 f23 = __half22float2(*reinterpret_cast<__half2*>(&raw.y));
        v[i] = make_float4(f01.x, f01.y, f23.x, f23.y);
    }
    float s = 0.f, sq = 0.f;
#pragma unroll
    for (int i = 0; i < 3; i++) {
        s  += v[i].x + v[i].y + v[i].z + v[i].w;
        sq += v[i].x*v[i].x + v[i].y*v[i].y + v[i].z*v[i].z + v[i].w*v[i].w;
    }
#pragma unroll
    for (int o = 16; o; o >>= 1) {
        s  += __shfl_xor_sync(0xffffffffu, s,  o);
        sq += __shfl_xor_sync(0xffffffffu, sq, o);
    }
    const float mean = s * (1.0f / Dd);
    const float var  = sq * (1.0f / Dd) - mean * mean;
    const float rstd = rsqrtf(var + 1e-5f);
    __half* orow = out + (size_t)row * Dd;
#pragma unroll
    for (int i = 0; i < 3; i++) {
        const int c = i * 128 + l * 4;
        const float4 gg = *(const float4*)(g + c);
        const float4 bb = *(const float4*)(be + c);
        uint2 o;
        o.x = pkhf((v[i].x - mean) * rstd * gg.x + bb.x,
                   (v[i].y - mean) * rstd * gg.y + bb.y);
        o.y = pkhf((v[i].z - mean) * rstd * gg.z + bb.z,
                   (v[i].w - mean) * rstd * gg.w + bb.w);
        *(uint2*)(orow + c) = o;
    }
}

// ------------------------------- fp16 HMMA GEMM (round-12/14 proven) -------------------------------
#define GOP_B   10240
#define GSTG_B  (2*GOP_B)
#define GNST    3
#define GEMM_SMEM (GNST*GSTG_B)  // 61440

template <int EPI, bool OHF, bool RESHF>
__global__ void __launch_bounds__(128, 3)
gemm_tc(const __half* __restrict__ A, const __half* __restrict__ B,
        void* __restrict__ Cv, int N, int K,
        const float* __restrict__ bias, const void* __restrict__ resid)
{
    extern __shared__ char smg[];
    const uint32_t s0 = smem_u32(smg);
    const int tid = threadIdx.x, w = tid >> 5, l = tid & 31;
    const int bn = blockIdx.x * 128, bm = blockIdx.y * 128;
    const int wm = w & 1, wn = w >> 1;

    const int lc = tid & 3, lr = tid >> 2;
    const __half* Ag = A + (size_t)(bm + lr) * K + lc * 8;
    const __half* Bg = B + (size_t)(bn + lr) * K + lc * 8;
    const uint32_t stoff = (uint32_t)(lr * 40 + lc * 8) * 2;

    uint32_t hacc[4][8][2];
#pragma unroll
    for (int i = 0; i < 4; i++)
#pragma unroll
        for (int j = 0; j < 8; j++) { hacc[i][j][0] = 0u; hacc[i][j][1] = 0u; }

    const int S = K / 32;

#define GA_ISSUE(p) do { \
    const uint32_t dst = s0 + ((p) % GNST) * GSTG_B; \
    const __half* ag = Ag + (p) * 32; \
    CPA(dst + stoff,          ag); \
    CPA(dst + stoff + 2560,   ag + (size_t)32 * K); \
    CPA(dst + stoff + 5120,   ag + (size_t)64 * K); \
    CPA(dst + stoff + 7680,   ag + (size_t)96 * K); \
} while (0)
#define GB_ISSUE(p) do { \
    const uint32_t dst = s0 + ((p) % GNST) * GSTG_B + GOP_B; \
    const __half* bg = Bg + (p) * 32; \
    CPA(dst + stoff,          bg); \
    CPA(dst + stoff + 2560,   bg + (size_t)32 * K); \
    CPA(dst + stoff + 5120,   bg + (size_t)64 * K); \
    CPA(dst + stoff + 7680,   bg + (size_t)96 * K); \
} while (0)

    GB_ISSUE(0); CPA_COMMIT();
    GB_ISSUE(1); CPA_COMMIT();
    GDC_WAIT();
    GA_ISSUE(0); CPA_COMMIT();
    GA_ISSUE(1); CPA_COMMIT();

    const int arow = ((l >> 3) & 1) * 8 + (l & 7);
    const uint32_t aBase = s0 + (uint32_t)((wm * 64 + arow) * 80) + (l >> 4) * 16;
    const int brow = (l >> 4) * 8 + (l & 7);
    const uint32_t bBase = s0 + GOP_B + (uint32_t)((wn * 64 + brow) * 80) + ((l >> 3) & 1) * 16;

    uint32_t af[4][4], bf[8][2];

#define G_LOADFRAG(ab, bb, ks) do { \
    _Pragma("unroll") \
    for (int mt = 0; mt < 4; mt++) \
        LDSM4(af[mt][0], af[mt][1], af[mt][2], af[mt][3], \
              (ab) + mt * 1280 + (ks) * 32); \
    _Pragma("unroll") \
    for (int pr = 0; pr < 4; pr++) { \
        uint32_t t0, t1, t2, t3; \
        LDSM4(t0, t1, t2, t3, (bb) + pr * 1280 + (ks) * 32); \
        bf[2*pr][0] = t0; bf[2*pr][1] = t1; \
        bf[2*pr+1][0] = t2; bf[2*pr+1][1] = t3; \
    } } while (0)

#define G_MMA() do { \
    _Pragma("unroll") \
    for (int mt = 0; mt < 4; mt++) \
        _Pragma("unroll") \
        for (int nt = 0; nt < 8; nt++) \
            MMA16816H(hacc[mt][nt], af[mt][0], af[mt][1], \
                      af[mt][2], af[mt][3], bf[nt][0], bf[nt][1]); \
    } while (0)

    for (int s = 0; s < S; s++) {
        asm volatile("cp.async.wait_group 1;" ::: "memory");
        __syncthreads();
        if (s + 2 < S) { GA_ISSUE(s + 2); GB_ISSUE(s + 2); }
        CPA_COMMIT();

        const uint32_t off = (uint32_t)((s % GNST) * GSTG_B);
        G_LOADFRAG(aBase + off, bBase + off, 0);
        G_MMA();
        G_LOADFRAG(aBase + off, bBase + off, 1);
        G_MMA();
    }
#undef GA_ISSUE
#undef GB_ISSUE
#undef G_LOADFRAG
#undef G_MMA

    GDC_TRIG();

    const int qr = l >> 2, qc = (l & 3) * 2;
#pragma unroll
    for (int mt = 0; mt < 4; mt++) {
#pragma unroll
        for (int half = 0; half < 2; half++) {
            const int r = bm + wm * 64 + mt * 16 + qr + half * 8;
#pragma unroll
            for (int nt = 0; nt < 8; nt++) {
                const int c = bn + wn * 64 + nt * 8 + qc;
                float2 vv = __half22float2(
                    *reinterpret_cast<__half2*>(&hacc[mt][nt][half]));
                float v0 = vv.x, v1 = vv.y;
                if (EPI & 1) { v0 += bias[c]; v1 += bias[c + 1]; }
                if (EPI & 2) { v0 = fmaxf(v0, 0.0f); v1 = fmaxf(v1, 0.0f); }
                if (EPI & 4) {
                    if (RESHF) {
                        uint32_t rr = *(const uint32_t*)((const __half*)resid + (size_t)r * N + c);
                        float2 rf = __half22float2(*reinterpret_cast<__half2*>(&rr));
                        v0 += rf.x; v1 += rf.y;
                    } else {
                        float2 rv = *(const float2*)((const float*)resid + (size_t)r * N + c);
                        v0 += rv.x; v1 += rv.y;
                    }
                }
                if (OHF) {
                    *(uint32_t*)((__half*)Cv + (size_t)r * N + c) = pkhf(v0, v1);
                } else {
                    *(float2*)((float*)Cv + (size_t)r * N + c) = make_float2(v0, v1);
                }
            }
        }
    }
}

// --------------------------- Attention (HMMA flash, software-pipelined) ---------------------------
// per chunk: QK(c) issued before PV(c-1); softmax(c) overlaps both MMA streams.
#define KV_PITCH 72

__global__ void __launch_bounds__(256, 3) attn_kernel(const __half* __restrict__ QKV,
                                                      __half* __restrict__ O)
{
    GDC_WAIT();
    extern __shared__ __align__(16) __half smkv[];
    const uint32_t sK = smem_u32(smkv);
    const uint32_t sV = sK + Tt * KV_PITCH * 2;
    const int bh = blockIdx.x;
    const int b = bh / Hh, h = bh % Hh;
    const int tid = threadIdx.x;
    const __half* base = QKV + (size_t)b * Tt * (3*Dd) + h * HD;

    for (int idx = tid; idx < 2 * 2048; idx += 256) {
        int half = idx >> 11, i = idx & 2047;
        int row = i >> 3, c8 = i & 7;
        const uint4 v = *(const uint4*)(base + (size_t)row * (3*Dd) + (half + 1) * Dd + c8 * 8);
        *(uint4*)((char*)smkv + (half ? (size_t)Tt * KV_PITCH * 2 : 0)
                  + row * (KV_PITCH*2) + c8 * 16) = v;
    }
    __syncthreads();

    const int w = tid >> 5, l = tid & 31;
    const int qr = l >> 2, qc = l & 3;

    const uint32_t kAddr = sK + (uint32_t)(((l >> 4) * 8 + (l & 7)) * (KV_PITCH*2))
                               + ((l >> 3) & 1) * 16;
    const uint32_t vAddr = sV + (uint32_t)((((l >> 3) & 1) * 8 + (l & 7)) * (KV_PITCH*2))
                               + ((l >> 4) & 1) * 16;

    const float sc2 = rsqrtf((float)Dd) * 1.4426950408889634f;

#pragma unroll
    for (int job = 0; job < 2; job++) {
        const int bt = job ? 16 * (15 - w) : 16 * w;
        const int nch = job ? (16 - w) : (w + 1);

        const __half* Qrow = base + (size_t)bt * (3*Dd);
        uint32_t qa[4][4];
#pragma unroll
        for (int kc = 0; kc < 4; kc++) {
            int k0 = kc * 16 + qc * 2;
            qa[kc][0] = *(const uint32_t*)(Qrow + (size_t)qr * (3*Dd) + k0);
            qa[kc][1] = *(const uint32_t*)(Qrow + (size_t)(qr + 8) * (3*Dd) + k0);
            qa[kc][2] = *(const uint32_t*)(Qrow + (size_t)qr * (3*Dd) + k0 + 8);
            qa[kc][3] = *(const uint32_t*)(Qrow + (size_t)(qr + 8) * (3*Dd) + k0 + 8);
        }

        float oacc[8][4];
#pragma unroll
        for (int i = 0; i < 8; i++)
#pragma unroll
            for (int j = 0; j < 4; j++) oacc[i][j] = 0.0f;
        float l0 = 0.0f, l1 = 0.0f;
        uint32_t pa0, pa1, pa2, pa3;   // probs of current chunk

        // QK for a chunk
#define A_QK(sacc, c) do { \
    const uint32_t kRow = kAddr + (c) * 16 * (KV_PITCH*2); \
    _Pragma("unroll") \
    for (int kc = 0; kc < 4; kc++) { \
        uint32_t k0, k1, k2, k3; \
        LDSM4(k0, k1, k2, k3, kRow + kc * 32); \
        MMA16816F(sacc[0], qa[kc][0], qa[kc][1], qa[kc][2], qa[kc][3], k0, k1); \
        MMA16816F(sacc[1], qa[kc][0], qa[kc][1], qa[kc][2], qa[kc][3], k2, k3); \
    } } while (0)

        // softmax of a chunk -> pa*, l*
#define A_SMAX(sacc, c) do { \
    const bool maskc = ((c) == nch - 1); \
    _Pragma("unroll") \
    for (int nt = 0; nt < 2; nt++) \
        _Pragma("unroll") \
        for (int j = 0; j < 4; j++) { \
            float sv = fminf(sacc[nt][j] * sc2, 10.0f); \
            if (maskc) { \
                int trow = bt + qr + 8 * (j >> 1); \
                int scol = 16 * (c) + 8 * nt + 2 * qc + (j & 1); \
                if (scol > trow) sv = -60000.0f; \
            } \
            sacc[nt][j] = sv; \
        } \
    PKH2(pa0, sacc[0][0], sacc[0][1]); \
    PKH2(pa1, sacc[0][2], sacc[0][3]); \
    PKH2(pa2, sacc[1][0], sacc[1][1]); \
    PKH2(pa3, sacc[1][2], sacc[1][3]); \
    EX2H2(pa0); EX2H2(pa1); EX2H2(pa2); EX2H2(pa3); \
    { \
        __half2 h0 = __hadd2(*reinterpret_cast<__half2*>(&pa0), \
                             *reinterpret_cast<__half2*>(&pa2)); \
        __half2 h1 = __hadd2(*reinterpret_cast<__half2*>(&pa1), \
                             *reinterpret_cast<__half2*>(&pa3)); \
        float2 f0 = __half22float2(h0), f1 = __half22float2(h1); \
        l0 += f0.x + f0.y; \
        l1 += f1.x + f1.y; \
    } } while (0)

        // PV for a chunk using current pa*
#define A_PV(c) do { \
    const uint32_t vRow = vAddr + (c) * 16 * (KV_PITCH*2); \
    _Pragma("unroll") \
    for (int g = 0; g < 4; g++) { \
        uint32_t v0, v1, v2, v3; \
        LDSM4T(v0, v1, v2, v3, vRow + g * 32); \
        MMA16816F(oacc[2*g],     pa0, pa1, pa2, pa3, v0, v1); \
        MMA16816F(oacc[2*g + 1], pa0, pa1, pa2, pa3, v2, v3); \
    } } while (0)

        // ---- pipelined loop: QK(c) || PV(c-1), then softmax(c)
        {
            float s[2][4];
#pragma unroll
            for (int nt = 0; nt < 2; nt++)
#pragma unroll
                for (int j = 0; j < 4; j++) s[nt][j] = 0.0f;
            A_QK(s, 0);
            A_SMAX(s, 0);
        }
        for (int c = 1; c < nch; c++) {
            float s[2][4];
#pragma unroll
            for (int nt = 0; nt < 2; nt++)
#pragma unroll
                for (int j = 0; j < 4; j++) s[nt][j] = 0.0f;
            A_QK(s, c);       // independent of pa (previous chunk)
            A_PV(c - 1);      // consumes pa; overlaps with QK above
            A_SMAX(s, c);     // produces new pa
        }
        A_PV(nch - 1);

#undef A_QK
#undef A_SMAX
#undef A_PV

        if (job == 1) GDC_TRIG();

        l0 += __shfl_xor_sync(0xffffffffu, l0, 1);
        l0 += __shfl_xor_sync(0xffffffffu, l0, 2);
        l1 += __shfl_xor_sync(0xffffffffu, l1, 1);
        l1 += __shfl_xor_sync(0xffffffffu, l1, 2);
        const float i0 = 1.0f / l0, i1 = 1.0f / l1;

        __half* Orow = O + ((size_t)b * Tt + bt) * Dd + h * HD;
#pragma unroll
        for (int dt = 0; dt < 8; dt++) {
            int col = dt * 8 + qc * 2;
            *(uint32_t*)(Orow + (size_t)qr * Dd + col) =
                pkhf(oacc[dt][0] * i0, oacc[dt][1] * i0);
            *(uint32_t*)(Orow + (size_t)(qr + 8) * Dd + col) =
                pkhf(oacc[dt][2] * i1, oacc[dt][3] * i1);
        }
    }
}

// ------------------------------- launch -------------------------------
template <typename F, typename... Args>
static void launch_pdl(F func, dim3 grid, dim3 block, size_t smem, Args... args)
{
    cudaLaunchConfig_t cfg = {};
    cfg.gridDim = grid; cfg.blockDim = block;
    cfg.dynamicSmemBytes = smem; cfg.stream = 0;
    cudaLaunchAttribute at[1];
    at[0].id = cudaLaunchAttributeProgrammaticStreamSerialization;
    at[0].val.programmaticStreamSerializationAllowed = 1;
    cfg.attrs = at; cfg.numAttrs = 1;
    cudaLaunchKernelEx(&cfg, func, args...);
}

extern "C" void kernel_launch(void* const* d_in, const int* in_sizes, int n_in,
                              void* d_out, int out_size)
{
    const float* x   = (const float*)d_in[0];
    const float* Wq  = (const float*)d_in[1];
    const float* Wk  = (const float*)d_in[2];
    const float* Wv  = (const float*)d_in[3];
    const float* Wp  = (const float*)d_in[4];
    const float* bp  = (const float*)d_in[5];
    const float* W1  = (const float*)d_in[6];
    const float* b1  = (const float*)d_in[7];
    const float* W2  = (const float*)d_in[8];
    const float* b2  = (const float*)d_in[9];
    const float* g1  = (const float*)d_in[10];
    const float* be1 = (const float*)d_in[11];
    const float* g2  = (const float*)d_in[12];
    const float* be2 = (const float*)d_in[13];
    float* out = (float*)d_out;

    __half *Hb, *Xh, *QKVb, *Ob, *X1h, *A1b, *WQKVt, *Wpt, *W1t, *W2t;
    cudaGetSymbolAddress((void**)&Hb,    g_Hb);
    cudaGetSymbolAddress((void**)&Xh,    g_Xh);
    cudaGetSymbolAddress((void**)&QKVb,  g_QKVb);
    cudaGetSymbolAddress((void**)&Ob,    g_Ob);
    cudaGetSymbolAddress((void**)&X1h,   g_X1h);
    cudaGetSymbolAddress((void**)&A1b,   g_A1b);
    cudaGetSymbolAddress((void**)&WQKVt, g_WQKVt);
    cudaGetSymbolAddress((void**)&Wpt,   g_Wpt);
    cudaGetSymbolAddress((void**)&W1t,   g_W1t);
    cudaGetSymbolAddress((void**)&W2t,   g_W2t);

    const int ATTN_SMEM = Tt * KV_PITCH * 2 * 2;  // 73728
    cudaFuncSetAttribute(attn_kernel, cudaFuncAttributeMaxDynamicSharedMemorySize, ATTN_SMEM);
    cudaFuncSetAttribute(gemm_tc<0, true, false>, cudaFuncAttributeMaxDynamicSharedMemorySize, GEMM_SMEM);
    cudaFuncSetAttribute(gemm_tc<5, true, true>,  cudaFuncAttributeMaxDynamicSharedMemorySize, GEMM_SMEM);
    cudaFuncSetAttribute(gemm_tc<3, true, false>, cudaFuncAttributeMaxDynamicSharedMemorySize, GEMM_SMEM);
    cudaFuncSetAttribute(gemm_tc<5, false, true>, cudaFuncAttributeMaxDynamicSharedMemorySize, GEMM_SMEM);

    // 1. LN1 + x->fp16 + weight pack
    ln1_pack<<<LN_BLKS + PK_BLKS, 256>>>(x, g1, be1, Hb, Xh,
                                         Wq, Wk, Wv, Wp, W1, W2,
                                         WQKVt, Wpt, W1t, W2t);
    // 2. QKV = Hb @ WQKVt^T
    launch_pdl(gemm_tc<0, true, false>, dim3((3*Dd)/128, ROWS/128), dim3(128), (size_t)GEMM_SMEM,
               (const __half*)Hb, (const __half*)WQKVt, (void*)QKVb, 3*Dd, Dd,
               (const float*)nullptr, (const void*)nullptr);
    // 3. attention -> Ob
    launch_pdl(attn_kernel, dim3(Bb*Hh), dim3(256), (size_t)ATTN_SMEM,
               (const __half*)QKVb, (__half*)Ob);
    // 4. X1h = fp16(xh + Ob @ Wpt^T + bp)  (fp16 resid)
    launch_pdl(gemm_tc<5, true, true>, dim3(Dd/128, ROWS/128), dim3(128), (size_t)GEMM_SMEM,
               (const __half*)Ob, (const __half*)Wpt, (void*)X1h, Dd, Dd,
               (const float*)bp, (const void*)Xh);
    // 5. LN2 -> Hb (fp16 in)
    launch_pdl(ln2_kernel, dim3(ROWS/8), dim3(256), (size_t)0,
               (const __half*)X1h, (const float*)g2, (const float*)be2, (__half*)Hb);
    // 6. A1 = relu(Hb @ W1t^T + b1)
    launch_pdl(gemm_tc<3, true, false>, dim3(DFF/128, ROWS/128), dim3(128), (size_t)GEMM_SMEM,
               (const __half*)Hb, (const __half*)W1t, (void*)A1b, DFF, Dd,
               (const float*)b1, (const void*)nullptr);
    // 7. out = X1h + A1 @ W2t^T + b2 (fp32 out, fp16 resid)
    launch_pdl(gemm_tc<5, false, true>, dim3(Dd/128, ROWS/128), dim3(128), (size_t)GEMM_SMEM,
               (const __half*)A1b, (const __half*)W2t, (void*)out, Dd, DFF,
               (const float*)b2, (const void*)X1h);
}